// round 5
// baseline (speedup 1.0000x reference)
#include <cuda_runtime.h>
#include <cuda_bf16.h>
#include <math.h>

#define NN 768
#define NJ 17
#define NPAIR (NN * NN)          // 589824
#define TILE_J 96                // j-tile per block (feat kernel)
#define WARPS_PER_BLOCK 8
#define AI 8                     // ass kernel i-tile
#define AJ 32                    // ass kernel j-tile

// -------- device scratch (no allocations allowed) --------
__device__ float g_vf[NN * 128];     // relu(vis_maps @ W_vis)
__device__ float g_av[NN * 128];     // g_vf ∘ wpv   (for logit term1)
__device__ float g_T1[NJ * 128];     // relu(W_cls_u)
__device__ float g_T2[NJ * 128];     // relu(W_cls_v)
__device__ float g_WL[2 * 128];      // combined W_loc (ch0+ch2, ch1+ch3)
__device__ float g_t2tab[NJ * NJ];   // cls-pair logit term
__device__ float g_nx[NN];           // x / 48
__device__ float g_ny[NN];           // y / 64

// ---------------- fused prep kernel ----------------
// blocks 0..767: vis_feat row i (+ a_i).  block 768: small tables.
__global__ void __launch_bounds__(128)
prep_all(const float* __restrict__ vm,
         const float* __restrict__ Wvis,
         const float* __restrict__ loc,
         const float* __restrict__ Wcu,
         const float* __restrict__ Wcv,
         const float* __restrict__ Wloc,
         const float* __restrict__ Wp) {
    const int b = blockIdx.x;
    const int t = threadIdx.x;  // 128 threads
    if (b < NN) {
        __shared__ float sv[32];
        if (t < 32) sv[t] = vm[b * 32 + t];
        __syncthreads();
        float acc = 0.0f;
#pragma unroll
        for (int k = 0; k < 32; k++)
            acc = fmaf(sv[k], __ldg(&Wvis[k * 128 + t]), acc);
        acc = fmaxf(acc, 0.0f);
        g_vf[b * 128 + t] = acc;
        g_av[b * 128 + t] = acc * Wp[t];   // fold wpv for logit term1
    } else {
        for (int idx = t; idx < NJ * 128; idx += 128) {
            g_T1[idx] = fmaxf(Wcu[idx], 0.0f);
            g_T2[idx] = fmaxf(Wcv[idx], 0.0f);
        }
        g_WL[t]       = Wloc[t]       + Wloc[2 * 128 + t];
        g_WL[128 + t] = Wloc[128 + t] + Wloc[3 * 128 + t];
        for (int i = t; i < NN; i += 128) {
            g_nx[i] = loc[i * 5 + 3] * (1.0f / 48.0f);
            g_ny[i] = loc[i * 5 + 4] * (1.0f / 64.0f);
        }
        // cls-pair table: t2tab[a][b] = sum_c relu(Wcu[a,c])*relu(Wcv[b,c])*wpc_c
        for (int e = t; e < NJ * NJ; e += 128) {
            const int a = e / NJ, bb = e % NJ;
            float s = 0.0f;
#pragma unroll 4
            for (int c = 0; c < 128; c++)
                s = fmaf(fmaxf(Wcu[a * 128 + c], 0.0f) * fmaxf(Wcv[bb * 128 + c], 0.0f),
                         Wp[128 + c], s);
            g_t2tab[e] = s;
        }
    }
}

// ---------------- helpers ----------------
__device__ __forceinline__ float4 mul4(float4 a, float4 b) {
    return make_float4(a.x * b.x, a.y * b.y, a.z * b.z, a.w * b.w);
}

// ---------------- feat kernel (pure streamer, no reduction) ----------------
__global__ void __launch_bounds__(WARPS_PER_BLOCK * 32, 6)
feat_main(const int* __restrict__ cls, float* __restrict__ out) {
    __shared__ float sT2[NJ * 128];
    __shared__ float s_nx[TILE_J];
    __shared__ float s_ny[TILE_J];
    __shared__ int   s_cls[TILE_J];

    const int j0 = blockIdx.y * TILE_J;
    for (int idx = threadIdx.x; idx < NJ * 128; idx += WARPS_PER_BLOCK * 32)
        sT2[idx] = g_T2[idx];
    if (threadIdx.x < TILE_J) {
        const int j = j0 + threadIdx.x;
        s_nx[threadIdx.x]  = g_nx[j];
        s_ny[threadIdx.x]  = g_ny[j];
        s_cls[threadIdx.x] = cls[j];
    }
    __syncthreads();

    const int warp = threadIdx.x >> 5;
    const int lane = threadIdx.x & 31;
    const int c4 = lane * 4;

    const int i = blockIdx.x * WARPS_PER_BLOCK + warp;  // row (0..767)

    const float4 vi  = *reinterpret_cast<const float4*>(&g_vf[i * 128 + c4]);
    const float4 f1  = *reinterpret_cast<const float4*>(&g_T1[cls[i] * 128 + c4]);
    const float4 wl0 = *reinterpret_cast<const float4*>(&g_WL[c4]);
    const float4 wl1 = *reinterpret_cast<const float4*>(&g_WL[128 + c4]);
    const float  nxi = g_nx[i];
    const float  nyi = g_ny[i];

    float* frow = out + (size_t)NPAIR + ((size_t)i * NN + j0) * 384;

#pragma unroll 4
    for (int jj = 0; jj < TILE_J; jj++) {
        const float4 vj = __ldg(reinterpret_cast<const float4*>(&g_vf[(j0 + jj) * 128 + c4]));
        const float4 f2 = *reinterpret_cast<const float4*>(&sT2[s_cls[jj] * 128 + c4]);
        const float dx = nxi - s_nx[jj];
        const float dy = nyi - s_ny[jj];
        const float g0 = dx * dx;
        const float g1 = dy * dy;

        const float4 v  = mul4(vi, vj);
        const float4 cl = mul4(f1, f2);
        float4 ge;
        ge.x = fmaxf(fmaf(g0, wl0.x, g1 * wl1.x), 0.0f);
        ge.y = fmaxf(fmaf(g0, wl0.y, g1 * wl1.y), 0.0f);
        ge.z = fmaxf(fmaf(g0, wl0.z, g1 * wl1.z), 0.0f);
        ge.w = fmaxf(fmaf(g0, wl0.w, g1 * wl1.w), 0.0f);

        float* p = frow + (size_t)jj * 384;
        __stcs(reinterpret_cast<float4*>(p + c4),       v);
        __stcs(reinterpret_cast<float4*>(p + 128 + c4), cl);
        __stcs(reinterpret_cast<float4*>(p + 256 + c4), ge);
    }
}

// ---------------- ass_maps kernel (thread-per-pair, recompute logit) ---------
__global__ void __launch_bounds__(AI * AJ)
ass_main(const int* __restrict__ cls,
         const float* __restrict__ Wp,
         float* __restrict__ out) {
    __shared__ float sa [AI][129];    // a_i rows
    __shared__ float svj[AJ][129];    // vj rows
    __shared__ float swl0[128], swl1[128], swpg[128];
    __shared__ float st2[NJ * NJ];
    __shared__ float s_nxi[AI], s_nyi[AI], s_nxj[AJ], s_nyj[AJ];
    __shared__ int   s_ci[AI], s_cj[AJ];

    const int i0 = blockIdx.x * AI;
    const int j0 = blockIdx.y * AJ;
    const int t  = threadIdx.x;   // 256

    for (int idx = t; idx < AI * 128; idx += AI * AJ)
        sa[idx >> 7][idx & 127] = g_av[(i0 + (idx >> 7)) * 128 + (idx & 127)];
    for (int idx = t; idx < AJ * 128; idx += AI * AJ)
        svj[idx >> 7][idx & 127] = g_vf[(j0 + (idx >> 7)) * 128 + (idx & 127)];
    if (t < 128) {
        swl0[t] = g_WL[t];
        swl1[t] = g_WL[128 + t];
        swpg[t] = Wp[256 + t];
    }
    for (int idx = t; idx < NJ * NJ; idx += AI * AJ)
        st2[idx] = g_t2tab[idx];
    if (t < AI) {
        s_nxi[t] = g_nx[i0 + t]; s_nyi[t] = g_ny[i0 + t]; s_ci[t] = cls[i0 + t];
    }
    if (t < AJ) {
        s_nxj[t] = g_nx[j0 + t]; s_nyj[t] = g_ny[j0 + t]; s_cj[t] = cls[j0 + t];
    }
    __syncthreads();

    const int w    = t >> 5;   // i within tile
    const int lane = t & 31;   // j within tile
    const float dx = s_nxi[w] - s_nxj[lane];
    const float dy = s_nyi[w] - s_nyj[lane];
    const float g0 = dx * dx;
    const float g1 = dy * dy;

    float acc = st2[s_ci[w] * NJ + s_cj[lane]];
#pragma unroll 4
    for (int c = 0; c < 128; c++) {
        acc = fmaf(sa[w][c], svj[lane][c], acc);                       // term1
        const float ge = fmaxf(fmaf(g0, swl0[c], g1 * swl1[c]), 0.0f); // term3
        acc = fmaf(ge, swpg[c], acc);
    }
    out[(size_t)(i0 + w) * NN + (j0 + lane)] = 1.0f / (1.0f + __expf(-acc));
}

// ---------------- launch ----------------
extern "C" void kernel_launch(void* const* d_in, const int* in_sizes, int n_in,
                              void* d_out, int out_size) {
    const float* vis_maps  = (const float*)d_in[0];  // [768, 32]
    const float* locations = (const float*)d_in[1];  // [768, 5]
    const int*   kpt_cls   = (const int*)d_in[2];    // [768]
    const float* W_cls_u   = (const float*)d_in[3];  // [17, 128]
    const float* W_cls_v   = (const float*)d_in[4];  // [17, 128]
    const float* W_loc     = (const float*)d_in[5];  // [4, 128]
    const float* W_vis     = (const float*)d_in[6];  // [32, 128]
    const float* W_pred    = (const float*)d_in[7];  // [384, 1]
    float* out = (float*)d_out;

    prep_all<<<NN + 1, 128>>>(vis_maps, W_vis, locations, W_cls_u, W_cls_v, W_loc, W_pred);

    dim3 agrid(NN / AI, NN / AJ);   // (96, 24)
    ass_main<<<agrid, AI * AJ>>>(kpt_cls, W_pred, out);

    dim3 fgrid(NN / WARPS_PER_BLOCK, NN / TILE_J);  // (96, 8)
    feat_main<<<fgrid, WARPS_PER_BLOCK * 32>>>(kpt_cls, out);
}

// round 6
// speedup vs baseline: 1.4608x; 1.4608x over previous
#include <cuda_runtime.h>
#include <cuda_bf16.h>
#include <math.h>

#define NN 768
#define NJ 17
#define NPAIR (NN * NN)          // 589824
#define TILE_J 32                // j-tile per block (small => many waves, tiny tail)
#define WARPS_PER_BLOCK 8

// -------- device scratch (no allocations allowed) --------
__device__ float g_vf[NN * 128];     // relu(vis_maps @ W_vis)
__device__ float g_T1[NJ * 128];     // relu(W_cls_u)
__device__ float g_T2[NJ * 128];     // relu(W_cls_v)
__device__ float g_WL[2 * 128];      // combined W_loc (ch0+ch2, ch1+ch3)
__device__ float g_nx[NN];           // x / 48
__device__ float g_ny[NN];           // y / 64

// ---------------- fused prep kernel (R4 version — cheap) ----------------
__global__ void __launch_bounds__(128)
prep_all(const float* __restrict__ vm,
         const float* __restrict__ Wvis,
         const float* __restrict__ loc,
         const float* __restrict__ Wcu,
         const float* __restrict__ Wcv,
         const float* __restrict__ Wloc) {
    const int b = blockIdx.x;
    const int t = threadIdx.x;  // 128 threads
    if (b < NN) {
        __shared__ float sv[32];
        if (t < 32) sv[t] = vm[b * 32 + t];
        __syncthreads();
        float acc = 0.0f;
#pragma unroll
        for (int k = 0; k < 32; k++)
            acc = fmaf(sv[k], __ldg(&Wvis[k * 128 + t]), acc);
        g_vf[b * 128 + t] = fmaxf(acc, 0.0f);
    } else {
        for (int idx = t; idx < NJ * 128; idx += 128) {
            g_T1[idx] = fmaxf(Wcu[idx], 0.0f);
            g_T2[idx] = fmaxf(Wcv[idx], 0.0f);
        }
        g_WL[t]       = Wloc[t]       + Wloc[2 * 128 + t];
        g_WL[128 + t] = Wloc[128 + t] + Wloc[3 * 128 + t];
        for (int i = t; i < NN; i += 128) {
            g_nx[i] = loc[i * 5 + 3] * (1.0f / 48.0f);
            g_ny[i] = loc[i * 5 + 4] * (1.0f / 64.0f);
        }
    }
}

// ---------------- helpers ----------------
__device__ __forceinline__ float4 mul4(float4 a, float4 b) {
    return make_float4(a.x * b.x, a.y * b.y, a.z * b.z, a.w * b.w);
}
__device__ __forceinline__ float dot4(float4 a, float4 b) {
    return fmaf(a.x, b.x, fmaf(a.y, b.y, fmaf(a.z, b.z, a.w * b.w)));
}
__device__ __forceinline__ float warp_sum(float v) {
#pragma unroll
    for (int off = 16; off; off >>= 1)
        v += __shfl_xor_sync(0xFFFFFFFFu, v, off);
    return v;
}

// ---------------- main kernel ----------------
__global__ void __launch_bounds__(WARPS_PER_BLOCK * 32)
assoc_main(const int* __restrict__ cls,
           const float* __restrict__ Wp,
           float* __restrict__ out) {
    __shared__ float sT2[NJ * 128];
    __shared__ float s_nx[TILE_J];
    __shared__ float s_ny[TILE_J];
    __shared__ int   s_cls[TILE_J];

    const int j0 = blockIdx.y * TILE_J;
    for (int idx = threadIdx.x; idx < NJ * 128; idx += WARPS_PER_BLOCK * 32)
        sT2[idx] = g_T2[idx];
    if (threadIdx.x < TILE_J) {
        const int j = j0 + threadIdx.x;
        s_nx[threadIdx.x]  = g_nx[j];
        s_ny[threadIdx.x]  = g_ny[j];
        s_cls[threadIdx.x] = cls[j];
    }
    __syncthreads();

    const int warp = threadIdx.x >> 5;
    const int lane = threadIdx.x & 31;
    const int c4 = lane * 4;

    const int i = blockIdx.x * WARPS_PER_BLOCK + warp;  // row (0..767)

    // i-invariant registers
    const float4 vi  = *reinterpret_cast<const float4*>(&g_vf[i * 128 + c4]);
    const float4 f1  = *reinterpret_cast<const float4*>(&g_T1[cls[i] * 128 + c4]);
    const float4 wpv = *reinterpret_cast<const float4*>(&Wp[c4]);
    const float4 wpc = *reinterpret_cast<const float4*>(&Wp[128 + c4]);
    const float4 wpg = *reinterpret_cast<const float4*>(&Wp[256 + c4]);
    const float4 wl0 = *reinterpret_cast<const float4*>(&g_WL[c4]);
    const float4 wl1 = *reinterpret_cast<const float4*>(&g_WL[128 + c4]);
    const float  nxi = g_nx[i];
    const float  nyi = g_ny[i];

    float* __restrict__ ass  = out;                       // [N, N]
    float* __restrict__ feat = out + (size_t)NPAIR;       // [N, N, 384]
    float* frow = feat + ((size_t)i * NN + j0) * 384;

#pragma unroll 4
    for (int jj = 0; jj < TILE_J; jj++) {
        const int j = j0 + jj;
        const float4 vj = __ldg(reinterpret_cast<const float4*>(&g_vf[j * 128 + c4]));
        const float4 f2 = *reinterpret_cast<const float4*>(&sT2[s_cls[jj] * 128 + c4]);
        const float dx = nxi - s_nx[jj];
        const float dy = nyi - s_ny[jj];
        const float g0 = dx * dx;
        const float g1 = dy * dy;

        const float4 v  = mul4(vi, vj);
        const float4 cl = mul4(f1, f2);
        float4 ge;
        ge.x = fmaxf(fmaf(g0, wl0.x, g1 * wl1.x), 0.0f);
        ge.y = fmaxf(fmaf(g0, wl0.y, g1 * wl1.y), 0.0f);
        ge.z = fmaxf(fmaf(g0, wl0.z, g1 * wl1.z), 0.0f);
        ge.w = fmaxf(fmaf(g0, wl0.w, g1 * wl1.w), 0.0f);

        float* p = frow + (size_t)jj * 384;
        __stcs(reinterpret_cast<float4*>(p + c4),       v);
        __stcs(reinterpret_cast<float4*>(p + 128 + c4), cl);
        __stcs(reinterpret_cast<float4*>(p + 256 + c4), ge);

        // logit: warp butterfly reduction
        float acc = dot4(v, wpv) + dot4(cl, wpc) + dot4(ge, wpg);
        acc = warp_sum(acc);
        if (lane == 0)
            __stcs(&ass[(size_t)i * NN + j], 1.0f / (1.0f + __expf(-acc)));
    }
}

// ---------------- launch ----------------
extern "C" void kernel_launch(void* const* d_in, const int* in_sizes, int n_in,
                              void* d_out, int out_size) {
    const float* vis_maps  = (const float*)d_in[0];  // [768, 32]
    const float* locations = (const float*)d_in[1];  // [768, 5]
    const int*   kpt_cls   = (const int*)d_in[2];    // [768]
    const float* W_cls_u   = (const float*)d_in[3];  // [17, 128]
    const float* W_cls_v   = (const float*)d_in[4];  // [17, 128]
    const float* W_loc     = (const float*)d_in[5];  // [4, 128]
    const float* W_vis     = (const float*)d_in[6];  // [32, 128]
    const float* W_pred    = (const float*)d_in[7];  // [384, 1]
    float* out = (float*)d_out;

    prep_all<<<NN + 1, 128>>>(vis_maps, W_vis, locations, W_cls_u, W_cls_v, W_loc);

    dim3 grid(NN / WARPS_PER_BLOCK, NN / TILE_J);  // (96, 24) = 2304 blocks
    assoc_main<<<grid, WARPS_PER_BLOCK * 32>>>(kpt_cls, W_pred, out);
}